// round 11
// baseline (speedup 1.0000x reference)
#include <cuda_runtime.h>
#include <cuda_bf16.h>
#include <stdint.h>
#include <math.h>

// Problem constants
#define BB 16
#define LL 512
#define NJ 4
#define NO 4
#define DD 64
#define SCALE 0.125f

#define LT 32          // l rows per block
#define THREADS 256
#define XP 72          // bf16 tile row stride (144B)

#define OUT_ELEMS (BB*LL*NO*DD)   // 2097152; attn follows
#define INP_ELEMS (BB*LL*NJ*DD)
#define W_ELEMS   (NO*NJ*DD*DD)

// smem byte offsets: two double-buffered x tiles (hi/lo), q (hi/lo), row sums
#define B0H 0
#define B0L 18432
#define B1H 36864
#define B1L 55296
#define QHO 73728
#define QLO 78336
#define SSO 82944
#define SMEM_BYTES 83456          // 2 CTAs/SM

// Pre-split bf16 hi/lo copies of inp and W
__device__ __align__(16) __nv_bfloat16 g_xh[INP_ELEMS];
__device__ __align__(16) __nv_bfloat16 g_xl[INP_ELEMS];
__device__ __align__(16) __nv_bfloat16 g_wh[W_ELEMS];
__device__ __align__(16) __nv_bfloat16 g_wl[W_ELEMS];

__device__ __forceinline__ uint32_t s2u(const void* p) {
    return (uint32_t)__cvta_generic_to_shared(p);
}
__device__ __forceinline__ void cpa16(uint32_t s, const void* g) {
    asm volatile("cp.async.ca.shared.global [%0], [%1], 16;" :: "r"(s), "l"(g));
}
#define CP_COMMIT() asm volatile("cp.async.commit_group;" ::: "memory")
#define CP_WAIT0()  asm volatile("cp.async.wait_group 0;" ::: "memory")
#define CP_WAIT1()  asm volatile("cp.async.wait_group 1;" ::: "memory")

__device__ __forceinline__ void ldm_x4(uint32_t a, uint32_t& r0, uint32_t& r1,
                                       uint32_t& r2, uint32_t& r3) {
    asm volatile("ldmatrix.sync.aligned.m8n8.x4.shared.b16 {%0,%1,%2,%3}, [%4];"
                 : "=r"(r0), "=r"(r1), "=r"(r2), "=r"(r3) : "r"(a));
}
__device__ __forceinline__ void ldm_x4t(uint32_t a, uint32_t& r0, uint32_t& r1,
                                        uint32_t& r2, uint32_t& r3) {
    asm volatile("ldmatrix.sync.aligned.m8n8.x4.trans.shared.b16 {%0,%1,%2,%3}, [%4];"
                 : "=r"(r0), "=r"(r1), "=r"(r2), "=r"(r3) : "r"(a));
}
__device__ __forceinline__ void mma_bf16(float* c, uint32_t a0, uint32_t a1,
                                         uint32_t a2, uint32_t a3,
                                         uint32_t b0, uint32_t b1) {
    asm volatile("mma.sync.aligned.m16n8k16.row.col.f32.bf16.bf16.f32 "
                 "{%0,%1,%2,%3},{%4,%5,%6,%7},{%8,%9},{%0,%1,%2,%3};"
                 : "+f"(c[0]), "+f"(c[1]), "+f"(c[2]), "+f"(c[3])
                 : "r"(a0), "r"(a1), "r"(a2), "r"(a3), "r"(b0), "r"(b1));
}
__device__ __forceinline__ uint32_t pack2(float x0, float x1) {
    __nv_bfloat162 v = __floats2bfloat162_rn(x0, x1);
    return *reinterpret_cast<uint32_t*>(&v);
}
__device__ __forceinline__ void split2(float x0, float x1, uint32_t& h, uint32_t& l) {
    float h0 = __bfloat162float(__float2bfloat16_rn(x0));
    float h1 = __bfloat162float(__float2bfloat16_rn(x1));
    h = pack2(x0, x1);
    l = pack2(x0 - h0, x1 - h1);
}
__device__ __forceinline__ void split4_u2(float4 v, uint2& H, uint2& L) {
    float h0 = __bfloat162float(__float2bfloat16_rn(v.x));
    float h1 = __bfloat162float(__float2bfloat16_rn(v.y));
    float h2 = __bfloat162float(__float2bfloat16_rn(v.z));
    float h3 = __bfloat162float(__float2bfloat16_rn(v.w));
    H = make_uint2(pack2(v.x, v.y), pack2(v.z, v.w));
    L = make_uint2(pack2(v.x - h0, v.y - h1), pack2(v.z - h2, v.w - h3));
}

// ======================= prologue: split inp/W into bf16 hi/lo =======================
__global__ void split_kernel(const float* __restrict__ inp, const float* __restrict__ W) {
    int idx = blockIdx.x * blockDim.x + threadIdx.x;
    if (idx < INP_ELEMS / 4) {
        float4 v = ((const float4*)inp)[idx];
        uint2 H, L;
        split4_u2(v, H, L);
        ((uint2*)g_xh)[idx] = H;
        ((uint2*)g_xl)[idx] = L;
    } else {
        int w = idx - INP_ELEMS / 4;
        if (w < W_ELEMS / 4) {
            float4 v = ((const float4*)W)[w];
            uint2 H, L;
            split4_u2(v, H, L);
            ((uint2*)g_wh)[w] = H;
            ((uint2*)g_wl)[w] = L;
        }
    }
}

// ======================= fused main kernel (double-buffered, no sS) =======================
__global__ __launch_bounds__(THREADS, 2)
void convattn_fused_kernel(float* __restrict__ out)
{
    extern __shared__ char smem[];
    const uint32_t sb = s2u(smem);
    const uint32_t qh_u = sb + QHO, ql_u = sb + QLO;
    float* ssum = (float*)(smem + SSO);          // [32][4]
    float* cbuf = (float*)smem;                  // final ctx merge (aliases buffers)

    const int tid  = threadIdx.x;
    const int warp = tid >> 5;
    const int lane = tid & 31;
    const int g = lane >> 2, t = lane & 3;
    const int lr = lane & 15, lc = (lane >> 4) * 8;

    const int l0g = blockIdx.x * LT;
    const int b   = blockIdx.y;
    const int o   = blockIdx.z;

    const int mw  = warp & 1;          // 2 m-tiles of 16 rows
    const int wq  = warp >> 1;         // 4-way m-chunk split
    const int lm0 = mw * 16;

    float* attn_out = out + OUT_ELEMS;

    float ctx_run[8][4];
    #pragma unroll
    for (int q = 0; q < 8; q++)
        #pragma unroll
        for (int i = 0; i < 4; i++) ctx_run[q][i] = 0.f;

    for (int j = 0; j < NJ; ++j) {
        // ---------- stage xl-tile (rows 0..31) + W (rows 64..127) into buf0 ----------
        #pragma unroll
        for (int it = 0; it < 2; it++) {
            int i = tid + it * THREADS;
            int sel = i >> 8, r = (i >> 3) & 31, ck = i & 7;
            const __nv_bfloat16* src = (sel ? g_xl : g_xh)
                + ((size_t)((b * LL + l0g + r) * NJ + j)) * DD + ck * 8;
            cpa16(sb + (sel ? B0L : B0H) + (r * XP + ck * 8) * 2, src);
        }
        #pragma unroll
        for (int it = 0; it < 4; it++) {
            int i = tid + it * THREADS;
            int sel = i >> 9, r = (i >> 3) & 63, ck = i & 7;
            const __nv_bfloat16* src = (sel ? g_wl : g_wh)
                + ((size_t)((o * NJ + j) * DD + r)) * DD + ck * 8;
            cpa16(sb + (sel ? B0L : B0H) + ((64 + r) * XP + ck * 8) * 2, src);
        }
        CP_COMMIT(); CP_WAIT0();
        __syncthreads();

        // prefetch chunk 0 -> buf1 (overlaps entire q phase)
        #pragma unroll
        for (int it = 0; it < 8; it++) {
            int i = tid + it * THREADS;
            int sel = i >> 10, r = (i >> 3) & 127, ck = i & 7;
            const __nv_bfloat16* src = (sel ? g_xl : g_xh)
                + ((size_t)((b * LL + r) * NJ + j)) * DD + ck * 8;
            cpa16(sb + (sel ? B1L : B1H) + (r * XP + ck * 8) * 2, src);
        }
        CP_COMMIT();

        // ---------- q = (xl @ W) * SCALE; warp tile 16 rows x 16 cols ----------
        {
            float qacc[2][4];
            #pragma unroll
            for (int q = 0; q < 2; q++)
                #pragma unroll
                for (int i = 0; i < 4; i++) qacc[q][i] = 0.f;
            #pragma unroll
            for (int ks = 0; ks < 4; ks++) {
                int k0 = ks * 16;
                uint32_t ah[4], al[4];
                uint32_t aoff = ((lm0 + lr) * XP + k0 + lc) * 2;
                ldm_x4(sb + B0H + aoff, ah[0], ah[1], ah[2], ah[3]);
                ldm_x4(sb + B0L + aoff, al[0], al[1], al[2], al[3]);
                int n0 = wq * 16;
                uint32_t bh[4], bl[4];
                uint32_t boff = ((64 + k0 + lr) * XP + n0 + lc) * 2;
                ldm_x4t(sb + B0H + boff, bh[0], bh[1], bh[2], bh[3]);
                ldm_x4t(sb + B0L + boff, bl[0], bl[1], bl[2], bl[3]);
                mma_bf16(qacc[0], ah[0],ah[1],ah[2],ah[3], bh[0],bh[1]);
                mma_bf16(qacc[0], al[0],al[1],al[2],al[3], bh[0],bh[1]);
                mma_bf16(qacc[0], ah[0],ah[1],ah[2],ah[3], bl[0],bl[1]);
                mma_bf16(qacc[1], ah[0],ah[1],ah[2],ah[3], bh[2],bh[3]);
                mma_bf16(qacc[1], al[0],al[1],al[2],al[3], bh[2],bh[3]);
                mma_bf16(qacc[1], ah[0],ah[1],ah[2],ah[3], bl[2],bl[3]);
            }
            #pragma unroll
            for (int q = 0; q < 2; q++) {
                int col = wq * 16 + q * 8 + t * 2;
                uint32_t h, l;
                split2(qacc[q][0] * SCALE, qacc[q][1] * SCALE, h, l);
                *(uint32_t*)(smem + QHO + ((lm0 + g) * XP + col) * 2) = h;
                *(uint32_t*)(smem + QLO + ((lm0 + g) * XP + col) * 2) = l;
                split2(qacc[q][2] * SCALE, qacc[q][3] * SCALE, h, l);
                *(uint32_t*)(smem + QHO + ((lm0 + g + 8) * XP + col) * 2) = h;
                *(uint32_t*)(smem + QLO + ((lm0 + g + 8) * XP + col) * 2) = l;
            }
        }
        __syncthreads();   // q visible; buf0 free for chunk-1 prefetch

        // ---------- fused chunks: S -> exp -> attn(unnormalized) + ctx MMA ----------
        float sj0 = 0.f, sj1 = 0.f;
        float ctx_j[8][4];
        #pragma unroll
        for (int q = 0; q < 8; q++)
            #pragma unroll
            for (int i = 0; i < 4; i++) ctx_j[q][i] = 0.f;

        float* apA = attn_out + ((size_t)(((o * NJ + j) * BB + b) * LL + l0g + lm0 + g)) * LL;
        float* apB = apA + 8 * LL;

        for (int c = 0; c < 4; c++) {
            // chunk c lives in buf1 (c even) / buf0 (c odd)
            const uint32_t rH = sb + ((c & 1) ? B0H : B1H);
            const uint32_t rL = sb + ((c & 1) ? B0L : B1L);
            if (c < 3) {   // prefetch c+1 into the other buffer (freed by c-1's bottom sync)
                const uint32_t nH = (c & 1) ? B1H : B0H;
                const uint32_t nL = (c & 1) ? B1L : B0L;
                #pragma unroll
                for (int it = 0; it < 8; it++) {
                    int i = tid + it * THREADS;
                    int sel = i >> 10, r = (i >> 3) & 127, ck = i & 7;
                    const __nv_bfloat16* src = (sel ? g_xl : g_xh)
                        + ((size_t)((b * LL + (c + 1) * 128 + r) * NJ + j)) * DD + ck * 8;
                    cpa16(sb + (sel ? nL : nH) + (r * XP + ck * 8) * 2, src);
                }
                CP_COMMIT();
                CP_WAIT1();          // chunk c arrived; c+1 stays in flight
            } else {
                CP_WAIT0();
            }
            __syncthreads();

            // S chunk: warp tile = 16 l-rows x 32 m-cols
            float p[4][4];
            #pragma unroll
            for (int q = 0; q < 4; q++)
                #pragma unroll
                for (int i = 0; i < 4; i++) p[q][i] = 0.f;

            #pragma unroll
            for (int ks = 0; ks < 4; ks++) {
                int k0 = ks * 16;
                uint32_t ah[4], al[4];
                uint32_t aoff = ((lm0 + lr) * XP + k0 + lc) * 2;
                ldm_x4(qh_u + aoff, ah[0], ah[1], ah[2], ah[3]);
                ldm_x4(ql_u + aoff, al[0], al[1], al[2], al[3]);
                #pragma unroll
                for (int rr = 0; rr < 2; rr++) {
                    int m0 = wq * 32 + rr * 16;
                    uint32_t bh[4], bl[4];
                    uint32_t boff = ((m0 + lc + (lane & 7)) * XP + k0 + ((lane >> 3) & 1) * 8) * 2;
                    ldm_x4(rH + boff, bh[0], bh[1], bh[2], bh[3]);
                    ldm_x4(rL + boff, bl[0], bl[1], bl[2], bl[3]);
                    mma_bf16(p[rr*2],   ah[0],ah[1],ah[2],ah[3], bh[0],bh[1]);
                    mma_bf16(p[rr*2],   al[0],al[1],al[2],al[3], bh[0],bh[1]);
                    mma_bf16(p[rr*2],   ah[0],ah[1],ah[2],ah[3], bl[0],bl[1]);
                    mma_bf16(p[rr*2+1], ah[0],ah[1],ah[2],ah[3], bh[2],bh[3]);
                    mma_bf16(p[rr*2+1], al[0],al[1],al[2],al[3], bh[2],bh[3]);
                    mma_bf16(p[rr*2+1], ah[0],ah[1],ah[2],ah[3], bl[2],bl[3]);
                }
            }

            // exp (no max: scores ~N(0,1), fp32-safe); write unnormalized attn; sums
            #pragma unroll
            for (int q = 0; q < 4; q++) {
                p[q][0] = __expf(p[q][0]); p[q][1] = __expf(p[q][1]);
                p[q][2] = __expf(p[q][2]); p[q][3] = __expf(p[q][3]);
                sj0 += p[q][0] + p[q][1];
                sj1 += p[q][2] + p[q][3];
                int col = c * 128 + wq * 32 + q * 8 + t * 2;
                *(float2*)(apA + col) = make_float2(p[q][0], p[q][1]);
                *(float2*)(apB + col) = make_float2(p[q][2], p[q][3]);
            }

            // ctx MMA: A = p (register-direct), k-slice = warp's 32 m-cols
            #pragma unroll
            for (int ks = 0; ks < 2; ks++) {
                uint32_t ah[4], al[4];
                split2(p[2*ks][0],   p[2*ks][1],   ah[0], al[0]);
                split2(p[2*ks][2],   p[2*ks][3],   ah[1], al[1]);
                split2(p[2*ks+1][0], p[2*ks+1][1], ah[2], al[2]);
                split2(p[2*ks+1][2], p[2*ks+1][3], ah[3], al[3]);
                int klr = wq * 32 + ks * 16;
                #pragma unroll
                for (int nt = 0; nt < 4; nt++) {
                    int n0 = nt * 16;
                    uint32_t bh[4], bl[4];
                    uint32_t boff = ((klr + lr) * XP + n0 + lc) * 2;
                    ldm_x4t(rH + boff, bh[0], bh[1], bh[2], bh[3]);
                    ldm_x4t(rL + boff, bl[0], bl[1], bl[2], bl[3]);
                    mma_bf16(ctx_j[nt*2],   ah[0],ah[1],ah[2],ah[3], bh[0],bh[1]);
                    mma_bf16(ctx_j[nt*2],   al[0],al[1],al[2],al[3], bh[0],bh[1]);
                    mma_bf16(ctx_j[nt*2],   ah[0],ah[1],ah[2],ah[3], bl[0],bl[1]);
                    mma_bf16(ctx_j[nt*2+1], ah[0],ah[1],ah[2],ah[3], bh[2],bh[3]);
                    mma_bf16(ctx_j[nt*2+1], al[0],al[1],al[2],al[3], bh[2],bh[3]);
                    mma_bf16(ctx_j[nt*2+1], ah[0],ah[1],ah[2],ah[3], bl[2],bl[3]);
                }
            }
            __syncthreads();   // all warps done reading this buffer
        } // chunks

        // ---------- merge row sums across wq (4 partials) ----------
        {
            float s0 = sj0, s1 = sj1;
            s0 += __shfl_xor_sync(0xffffffffu, s0, 1);
            s0 += __shfl_xor_sync(0xffffffffu, s0, 2);
            s1 += __shfl_xor_sync(0xffffffffu, s1, 1);
            s1 += __shfl_xor_sync(0xffffffffu, s1, 2);
            if (t == 0) {
                ssum[(lm0 + g) * 4 + wq]     = s0;
                ssum[(lm0 + g + 8) * 4 + wq] = s1;
            }
        }
        __syncthreads();

        {
            int ra = (lm0 + g) * 4, rb = (lm0 + g + 8) * 4;
            float inv_a = 1.f / (ssum[ra] + ssum[ra+1] + ssum[ra+2] + ssum[ra+3]);
            float inv_b = 1.f / (ssum[rb] + ssum[rb+1] + ssum[rb+2] + ssum[rb+3]);

            // fold normalized ctx_j into ctx_run
            #pragma unroll
            for (int q = 0; q < 8; q++) {
                ctx_run[q][0] += ctx_j[q][0] * inv_a;
                ctx_run[q][1] += ctx_j[q][1] * inv_a;
                ctx_run[q][2] += ctx_j[q][2] * inv_b;
                ctx_run[q][3] += ctx_j[q][3] * inv_b;
            }

            // in-place rescale of this thread's own attn cells (L2-hot, same-thread RMW)
            #pragma unroll
            for (int c = 0; c < 4; c++) {
                #pragma unroll
                for (int q = 0; q < 4; q++) {
                    int col = c * 128 + wq * 32 + q * 8 + t * 2;
                    float2 va = *(float2*)(apA + col);
                    va.x *= inv_a; va.y *= inv_a;
                    *(float2*)(apA + col) = va;
                    float2 vb = *(float2*)(apB + col);
                    vb.x *= inv_b; vb.y *= inv_b;
                    *(float2*)(apB + col) = vb;
                }
            }
        }
        // next j's stage-wait sync orders ssum reads vs overwrites
    } // j

    // ---------- 4-way (wq) ctx merge via cbuf + out write ----------
    __syncthreads();
    if (wq != 0) {
        #pragma unroll
        for (int q = 0; q < 8; q++) {
            int col = (q >> 1) * 16 + (q & 1) * 8 + t * 2;
            *(float2*)(cbuf + ((wq * 32 + lm0 + g) * 68) + col) =
                make_float2(ctx_run[q][0], ctx_run[q][1]);
            *(float2*)(cbuf + ((wq * 32 + lm0 + g + 8) * 68) + col) =
                make_float2(ctx_run[q][2], ctx_run[q][3]);
        }
    }
    __syncthreads();
    if (wq == 0) {
        #pragma unroll
        for (int q = 0; q < 8; q++) {
            int col = (q >> 1) * 16 + (q & 1) * 8 + t * 2;
            float a0 = ctx_run[q][0], a1 = ctx_run[q][1];
            float b0 = ctx_run[q][2], b1 = ctx_run[q][3];
            #pragma unroll
            for (int w = 1; w < 4; w++) {
                float2 v0 = *(float2*)(cbuf + ((w * 32 + lm0 + g) * 68) + col);
                float2 v1 = *(float2*)(cbuf + ((w * 32 + lm0 + g + 8) * 68) + col);
                a0 += v0.x; a1 += v0.y; b0 += v1.x; b1 += v1.y;
            }
            int r0 = l0g + lm0 + g;
            *(float2*)(out + ((size_t)(b * LL + r0) * NO + o) * DD + col) =
                make_float2(a0 * 0.25f, a1 * 0.25f);
            *(float2*)(out + ((size_t)(b * LL + r0 + 8) * NO + o) * DD + col) =
                make_float2(b0 * 0.25f, b1 * 0.25f);
        }
    }
}

extern "C" void kernel_launch(void* const* d_in, const int* in_sizes, int n_in,
                              void* d_out, int out_size) {
    const float* inp = (const float*)d_in[0];   // [16,512,4,64]
    const float* W   = (const float*)d_in[1];   // [4,4,64,64]
    float* out = (float*)d_out;

    static int smem_set = 0;
    if (!smem_set) {
        cudaFuncSetAttribute(convattn_fused_kernel,
                             cudaFuncAttributeMaxDynamicSharedMemorySize, SMEM_BYTES);
        smem_set = 1;
    }

    int total4 = INP_ELEMS / 4 + W_ELEMS / 4;
    split_kernel<<<(total4 + THREADS - 1) / THREADS, THREADS>>>(inp, W);

    dim3 grid(LL / LT, BB, NO);   // (16, 16, 4)
    convattn_fused_kernel<<<grid, THREADS, SMEM_BYTES>>>(out);
}

// round 14
// speedup vs baseline: 1.0955x; 1.0955x over previous
#include <cuda_runtime.h>
#include <cuda_bf16.h>
#include <stdint.h>
#include <math.h>

// Problem constants
#define BB 16
#define LL 512
#define NJ 4
#define NO 4
#define DD 64
#define SCALE 0.125f

#define LT 32          // l rows per block
#define THREADS 256
#define XP 72          // bf16 tile row stride (144B)
#define SCP 132        // chunk-sS row stride (floats)

#define OUT_ELEMS (BB*LL*NO*DD)   // 2097152; attn follows
#define INP_ELEMS (BB*LL*NJ*DD)
#define W_ELEMS   (NO*NJ*DD*DD)

// smem byte offsets
#define B0H 0
#define B0L 18432
#define B1H 36864
#define B1L 55296
#define QHO 73728
#define QLO 78336
#define SSC 82944     // chunk exp buffer: 32 x 132 fp32 = 16896
#define SSO 99840     // row-sum partials [32][4]
#define SMEM_BYTES 100352   // 2 CTAs/SM

// Pre-split bf16 hi/lo copies of inp and W
__device__ __align__(16) __nv_bfloat16 g_xh[INP_ELEMS];
__device__ __align__(16) __nv_bfloat16 g_xl[INP_ELEMS];
__device__ __align__(16) __nv_bfloat16 g_wh[W_ELEMS];
__device__ __align__(16) __nv_bfloat16 g_wl[W_ELEMS];

__device__ __forceinline__ uint32_t s2u(const void* p) {
    return (uint32_t)__cvta_generic_to_shared(p);
}
__device__ __forceinline__ void cpa16(uint32_t s, const void* g) {
    asm volatile("cp.async.ca.shared.global [%0], [%1], 16;" :: "r"(s), "l"(g));
}
#define CP_COMMIT() asm volatile("cp.async.commit_group;" ::: "memory")
#define CP_WAIT0()  asm volatile("cp.async.wait_group 0;" ::: "memory")
#define CP_WAIT1()  asm volatile("cp.async.wait_group 1;" ::: "memory")

__device__ __forceinline__ void ldm_x4(uint32_t a, uint32_t& r0, uint32_t& r1,
                                       uint32_t& r2, uint32_t& r3) {
    asm volatile("ldmatrix.sync.aligned.m8n8.x4.shared.b16 {%0,%1,%2,%3}, [%4];"
                 : "=r"(r0), "=r"(r1), "=r"(r2), "=r"(r3) : "r"(a));
}
__device__ __forceinline__ void ldm_x4t(uint32_t a, uint32_t& r0, uint32_t& r1,
                                        uint32_t& r2, uint32_t& r3) {
    asm volatile("ldmatrix.sync.aligned.m8n8.x4.trans.shared.b16 {%0,%1,%2,%3}, [%4];"
                 : "=r"(r0), "=r"(r1), "=r"(r2), "=r"(r3) : "r"(a));
}
__device__ __forceinline__ void mma_bf16(float* c, uint32_t a0, uint32_t a1,
                                         uint32_t a2, uint32_t a3,
                                         uint32_t b0, uint32_t b1) {
    asm volatile("mma.sync.aligned.m16n8k16.row.col.f32.bf16.bf16.f32 "
                 "{%0,%1,%2,%3},{%4,%5,%6,%7},{%8,%9},{%0,%1,%2,%3};"
                 : "+f"(c[0]), "+f"(c[1]), "+f"(c[2]), "+f"(c[3])
                 : "r"(a0), "r"(a1), "r"(a2), "r"(a3), "r"(b0), "r"(b1));
}
__device__ __forceinline__ uint32_t pack2(float x0, float x1) {
    __nv_bfloat162 v = __floats2bfloat162_rn(x0, x1);
    return *reinterpret_cast<uint32_t*>(&v);
}
__device__ __forceinline__ void split2(float x0, float x1, uint32_t& h, uint32_t& l) {
    float h0 = __bfloat162float(__float2bfloat16_rn(x0));
    float h1 = __bfloat162float(__float2bfloat16_rn(x1));
    h = pack2(x0, x1);
    l = pack2(x0 - h0, x1 - h1);
}
__device__ __forceinline__ void split4_u2(float4 v, uint2& H, uint2& L) {
    float h0 = __bfloat162float(__float2bfloat16_rn(v.x));
    float h1 = __bfloat162float(__float2bfloat16_rn(v.y));
    float h2 = __bfloat162float(__float2bfloat16_rn(v.z));
    float h3 = __bfloat162float(__float2bfloat16_rn(v.w));
    H = make_uint2(pack2(v.x, v.y), pack2(v.z, v.w));
    L = make_uint2(pack2(v.x - h0, v.y - h1), pack2(v.z - h2, v.w - h3));
}

// ======================= prologue: split inp/W into bf16 hi/lo =======================
__global__ void split_kernel(const float* __restrict__ inp, const float* __restrict__ W) {
    int idx = blockIdx.x * blockDim.x + threadIdx.x;
    if (idx < INP_ELEMS / 4) {
        float4 v = ((const float4*)inp)[idx];
        uint2 H, L;
        split4_u2(v, H, L);
        ((uint2*)g_xh)[idx] = H;
        ((uint2*)g_xl)[idx] = L;
    } else {
        int w = idx - INP_ELEMS / 4;
        if (w < W_ELEMS / 4) {
            float4 v = ((const float4*)W)[w];
            uint2 H, L;
            split4_u2(v, H, L);
            ((uint2*)g_wh)[w] = H;
            ((uint2*)g_wl)[w] = L;
        }
    }
}

// ============== fused kernel: double-buffered + chunk-sS coalescing ==============
__global__ __launch_bounds__(THREADS, 2)
void convattn_fused_kernel(float* __restrict__ out)
{
    extern __shared__ char smem[];
    const uint32_t sb = s2u(smem);
    const uint32_t qh_u = sb + QHO, ql_u = sb + QLO;
    float* sSc  = (float*)(smem + SSC);          // [32][132] chunk exp
    float* ssum = (float*)(smem + SSO);          // [32][4]
    float* cbuf = (float*)smem;                  // final ctx merge (aliases x buffers)

    const int tid  = threadIdx.x;
    const int warp = tid >> 5;
    const int lane = tid & 31;
    const int g = lane >> 2, t = lane & 3;
    const int lr = lane & 15, lc = (lane >> 4) * 8;

    const int l0g = blockIdx.x * LT;
    const int b   = blockIdx.y;
    const int o   = blockIdx.z;

    const int mw  = warp & 1;          // 2 m-tiles of 16 rows
    const int wq  = warp >> 1;         // 4-way m-chunk split
    const int lm0 = mw * 16;

    float* attn_out = out + OUT_ELEMS;

    float ctx_run[8][4];
    #pragma unroll
    for (int q = 0; q < 8; q++)
        #pragma unroll
        for (int i = 0; i < 4; i++) ctx_run[q][i] = 0.f;

    for (int j = 0; j < NJ; ++j) {
        // ---------- stage xl-tile (rows 0..31) + W (rows 64..127) into buf0 ----------
        #pragma unroll
        for (int it = 0; it < 2; it++) {
            int i = tid + it * THREADS;
            int sel = i >> 8, r = (i >> 3) & 31, ck = i & 7;
            const __nv_bfloat16* src = (sel ? g_xl : g_xh)
                + ((size_t)((b * LL + l0g + r) * NJ + j)) * DD + ck * 8;
            cpa16(sb + (sel ? B0L : B0H) + (r * XP + ck * 8) * 2, src);
        }
        #pragma unroll
        for (int it = 0; it < 4; it++) {
            int i = tid + it * THREADS;
            int sel = i >> 9, r = (i >> 3) & 63, ck = i & 7;
            const __nv_bfloat16* src = (sel ? g_wl : g_wh)
                + ((size_t)((o * NJ + j) * DD + r)) * DD + ck * 8;
            cpa16(sb + (sel ? B0L : B0H) + ((64 + r) * XP + ck * 8) * 2, src);
        }
        CP_COMMIT(); CP_WAIT0();
        __syncthreads();

        // prefetch chunk 0 -> buf1 (overlaps entire q phase)
        #pragma unroll
        for (int it = 0; it < 8; it++) {
            int i = tid + it * THREADS;
            int sel = i >> 10, r = (i >> 3) & 127, ck = i & 7;
            const __nv_bfloat16* src = (sel ? g_xl : g_xh)
                + ((size_t)((b * LL + r) * NJ + j)) * DD + ck * 8;
            cpa16(sb + (sel ? B1L : B1H) + (r * XP + ck * 8) * 2, src);
        }
        CP_COMMIT();

        // ---------- q = (xl @ W) * SCALE; warp tile 16 rows x 16 cols ----------
        {
            float qacc[2][4];
            #pragma unroll
            for (int q = 0; q < 2; q++)
                #pragma unroll
                for (int i = 0; i < 4; i++) qacc[q][i] = 0.f;
            #pragma unroll
            for (int ks = 0; ks < 4; ks++) {
                int k0 = ks * 16;
                uint32_t ah[4], al[4];
                uint32_t aoff = ((lm0 + lr) * XP + k0 + lc) * 2;
                ldm_x4(sb + B0H + aoff, ah[0], ah[1], ah[2], ah[3]);
                ldm_x4(sb + B0L + aoff, al[0], al[1], al[2], al[3]);
                int n0 = wq * 16;
                uint32_t bh[4], bl[4];
                uint32_t boff = ((64 + k0 + lr) * XP + n0 + lc) * 2;
                ldm_x4t(sb + B0H + boff, bh[0], bh[1], bh[2], bh[3]);
                ldm_x4t(sb + B0L + boff, bl[0], bl[1], bl[2], bl[3]);
                mma_bf16(qacc[0], ah[0],ah[1],ah[2],ah[3], bh[0],bh[1]);
                mma_bf16(qacc[0], al[0],al[1],al[2],al[3], bh[0],bh[1]);
                mma_bf16(qacc[0], ah[0],ah[1],ah[2],ah[3], bl[0],bl[1]);
                mma_bf16(qacc[1], ah[0],ah[1],ah[2],ah[3], bh[2],bh[3]);
                mma_bf16(qacc[1], al[0],al[1],al[2],al[3], bh[2],bh[3]);
                mma_bf16(qacc[1], ah[0],ah[1],ah[2],ah[3], bl[2],bl[3]);
            }
            #pragma unroll
            for (int q = 0; q < 2; q++) {
                int col = wq * 16 + q * 8 + t * 2;
                uint32_t h, l;
                split2(qacc[q][0] * SCALE, qacc[q][1] * SCALE, h, l);
                *(uint32_t*)(smem + QHO + ((lm0 + g) * XP + col) * 2) = h;
                *(uint32_t*)(smem + QLO + ((lm0 + g) * XP + col) * 2) = l;
                split2(qacc[q][2] * SCALE, qacc[q][3] * SCALE, h, l);
                *(uint32_t*)(smem + QHO + ((lm0 + g + 8) * XP + col) * 2) = h;
                *(uint32_t*)(smem + QLO + ((lm0 + g + 8) * XP + col) * 2) = l;
            }
        }
        __syncthreads();   // q visible; buf0 free for chunk-1 prefetch

        // ---------- fused chunks ----------
        float sj0 = 0.f, sj1 = 0.f;
        float ctx_j[8][4];
        #pragma unroll
        for (int q = 0; q < 8; q++)
            #pragma unroll
            for (int i = 0; i < 4; i++) ctx_j[q][i] = 0.f;

        float* apw = attn_out + ((size_t)(((o * NJ + j) * BB + b) * LL + l0g)) * LL;

        for (int c = 0; c < 4; c++) {
            // chunk c lives in buf1 (c even) / buf0 (c odd)
            const uint32_t rH = sb + ((c & 1) ? B0H : B1H);
            const uint32_t rL = sb + ((c & 1) ? B0L : B1L);
            if (c < 3) {   // prefetch c+1 into the other buffer
                const uint32_t nH = (c & 1) ? B1H : B0H;
                const uint32_t nL = (c & 1) ? B1L : B0L;
                #pragma unroll
                for (int it = 0; it < 8; it++) {
                    int i = tid + it * THREADS;
                    int sel = i >> 10, r = (i >> 3) & 127, ck = i & 7;
                    const __nv_bfloat16* src = (sel ? g_xl : g_xh)
                        + ((size_t)((b * LL + (c + 1) * 128 + r) * NJ + j)) * DD + ck * 8;
                    cpa16(sb + (sel ? nL : nH) + (r * XP + ck * 8) * 2, src);
                }
                CP_COMMIT();
                CP_WAIT1();          // chunk c arrived; c+1 stays in flight
            } else {
                CP_WAIT0();
            }
            __syncthreads();

            // S chunk: warp tile = 16 l-rows x 32 m-cols
            float p[4][4];
            #pragma unroll
            for (int q = 0; q < 4; q++)
                #pragma unroll
                for (int i = 0; i < 4; i++) p[q][i] = 0.f;

            #pragma unroll
            for (int ks = 0; ks < 4; ks++) {
                int k0 = ks * 16;
                uint32_t ah[4], al[4];
                uint32_t aoff = ((lm0 + lr) * XP + k0 + lc) * 2;
                ldm_x4(qh_u + aoff, ah[0], ah[1], ah[2], ah[3]);
                ldm_x4(ql_u + aoff, al[0], al[1], al[2], al[3]);
                #pragma unroll
                for (int rr = 0; rr < 2; rr++) {
                    int m0 = wq * 32 + rr * 16;
                    uint32_t bh[4], bl[4];
                    uint32_t boff = ((m0 + lc + (lane & 7)) * XP + k0 + ((lane >> 3) & 1) * 8) * 2;
                    ldm_x4(rH + boff, bh[0], bh[1], bh[2], bh[3]);
                    ldm_x4(rL + boff, bl[0], bl[1], bl[2], bl[3]);
                    mma_bf16(p[rr*2],   ah[0],ah[1],ah[2],ah[3], bh[0],bh[1]);
                    mma_bf16(p[rr*2],   al[0],al[1],al[2],al[3], bh[0],bh[1]);
                    mma_bf16(p[rr*2],   ah[0],ah[1],ah[2],ah[3], bl[0],bl[1]);
                    mma_bf16(p[rr*2+1], ah[0],ah[1],ah[2],ah[3], bh[2],bh[3]);
                    mma_bf16(p[rr*2+1], al[0],al[1],al[2],al[3], bh[2],bh[3]);
                    mma_bf16(p[rr*2+1], ah[0],ah[1],ah[2],ah[3], bl[2],bl[3]);
                }
            }

            // exp (no max: scores ~N(0,1), fp32-safe); sums; stage chunk into sSc
            #pragma unroll
            for (int q = 0; q < 4; q++) {
                p[q][0] = __expf(p[q][0]); p[q][1] = __expf(p[q][1]);
                p[q][2] = __expf(p[q][2]); p[q][3] = __expf(p[q][3]);
                sj0 += p[q][0] + p[q][1];
                sj1 += p[q][2] + p[q][3];
                int col = wq * 32 + q * 8 + t * 2;      // chunk-local column
                *(float2*)(sSc + (lm0 + g)     * SCP + col) = make_float2(p[q][0], p[q][1]);
                *(float2*)(sSc + (lm0 + g + 8) * SCP + col) = make_float2(p[q][2], p[q][3]);
            }

            // ctx MMA: A = p (register-direct), k-slice = warp's 32 m-cols
            #pragma unroll
            for (int ks = 0; ks < 2; ks++) {
                uint32_t ah[4], al[4];
                split2(p[2*ks][0],   p[2*ks][1],   ah[0], al[0]);
                split2(p[2*ks][2],   p[2*ks][3],   ah[1], al[1]);
                split2(p[2*ks+1][0], p[2*ks+1][1], ah[2], al[2]);
                split2(p[2*ks+1][2], p[2*ks+1][3], ah[3], al[3]);
                int klr = wq * 32 + ks * 16;
                #pragma unroll
                for (int nt = 0; nt < 4; nt++) {
                    int n0 = nt * 16;
                    uint32_t bh[4], bl[4];
                    uint32_t boff = ((klr + lr) * XP + n0 + lc) * 2;
                    ldm_x4t(rH + boff, bh[0], bh[1], bh[2], bh[3]);
                    ldm_x4t(rL + boff, bl[0], bl[1], bl[2], bl[3]);
                    mma_bf16(ctx_j[nt*2],   ah[0],ah[1],ah[2],ah[3], bh[0],bh[1]);
                    mma_bf16(ctx_j[nt*2],   al[0],al[1],al[2],al[3], bh[0],bh[1]);
                    mma_bf16(ctx_j[nt*2],   ah[0],ah[1],ah[2],ah[3], bl[0],bl[1]);
                    mma_bf16(ctx_j[nt*2+1], ah[0],ah[1],ah[2],ah[3], bh[2],bh[3]);
                    mma_bf16(ctx_j[nt*2+1], al[0],al[1],al[2],al[3], bh[2],bh[3]);
                    mma_bf16(ctx_j[nt*2+1], ah[0],ah[1],ah[2],ah[3], bl[2],bl[3]);
                }
            }
            __syncthreads();   // sSc complete; x buffer free

            // coalesced write of unnormalized exp chunk: warp = 4 rows x 128 cols
            #pragma unroll
            for (int r = 0; r < 4; r++) {
                int l = warp * 4 + r;
                float4 v = *(float4*)(sSc + l * SCP + lane * 4);
                *(float4*)(apw + (size_t)l * LL + c * 128 + lane * 4) = v;
            }
        } // chunks

        // ---------- merge row sums across wq (4 partials) ----------
        {
            float s0 = sj0, s1 = sj1;
            s0 += __shfl_xor_sync(0xffffffffu, s0, 1);
            s0 += __shfl_xor_sync(0xffffffffu, s0, 2);
            s1 += __shfl_xor_sync(0xffffffffu, s1, 1);
            s1 += __shfl_xor_sync(0xffffffffu, s1, 2);
            if (t == 0) {
                ssum[(lm0 + g) * 4 + wq]     = s0;
                ssum[(lm0 + g + 8) * 4 + wq] = s1;
            }
        }
        __syncthreads();

        // coalesced in-place attn rescale (same threads wrote these lines; L2-hot)
        #pragma unroll 1
        for (int r = 0; r < 4; r++) {
            int l = warp * 4 + r;
            float inv = 1.f / (ssum[l*4] + ssum[l*4+1] + ssum[l*4+2] + ssum[l*4+3]);
            float* row = apw + (size_t)l * LL;
            #pragma unroll
            for (int tt = 0; tt < 4; tt++) {
                float4 v = *(float4*)(row + lane * 4 + tt * 128);
                v.x *= inv; v.y *= inv; v.z *= inv; v.w *= inv;
                *(float4*)(row + lane * 4 + tt * 128) = v;
            }
        }

        // fold normalized ctx_j into ctx_run
        {
            int ra = (lm0 + g) * 4, rb = (lm0 + g + 8) * 4;
            float inv_a = 1.f / (ssum[ra] + ssum[ra+1] + ssum[ra+2] + ssum[ra+3]);
            float inv_b = 1.f / (ssum[rb] + ssum[rb+1] + ssum[rb+2] + ssum[rb+3]);
            #pragma unroll
            for (int q = 0; q < 8; q++) {
                ctx_run[q][0] += ctx_j[q][0] * inv_a;
                ctx_run[q][1] += ctx_j[q][1] * inv_a;
                ctx_run[q][2] += ctx_j[q][2] * inv_b;
                ctx_run[q][3] += ctx_j[q][3] * inv_b;
            }
        }
        __syncthreads();   // ssum free for next j
    } // j

    // ---------- 4-way (wq) ctx merge via cbuf + out write ----------
    if (wq != 0) {
        #pragma unroll
        for (int q = 0; q < 8; q++) {
            int col = (q >> 1) * 16 + (q & 1) * 8 + t * 2;
            *(float2*)(cbuf + ((wq * 32 + lm0 + g) * 68) + col) =
                make_float2(ctx_run[q][0], ctx_run[q][1]);
            *(float2*)(cbuf + ((wq * 32 + lm0 + g + 8) * 68) + col) =
                make_float2(ctx_run[q][2], ctx_run[q][3]);
        }
    }
    __syncthreads();
    if (wq == 0) {
        #pragma unroll
        for (int q = 0; q < 8; q++) {
            int col = (q >> 1) * 16 + (q & 1) * 8 + t * 2;
            float a0 = ctx_run[q][0], a1 = ctx_run[q][1];
            float b0 = ctx_run[q][2], b1 = ctx_run[q][3];
            #pragma unroll
            for (int w = 1; w < 4; w++) {
                float2 v0 = *(float2*)(cbuf + ((w * 32 + lm0 + g) * 68) + col);
                float2 v1 = *(float2*)(cbuf + ((w * 32 + lm0 + g + 8) * 68) + col);
                a0 += v0.x; a1 += v0.y; b0 += v1.x; b1 += v1.y;
            }
            int r0 = l0g + lm0 + g;
            *(float2*)(out + ((size_t)(b * LL + r0) * NO + o) * DD + col) =
                make_float2(a0 * 0.25f, a1 * 0.25f);
            *(float2*)(out + ((size_t)(b * LL + r0 + 8) * NO + o) * DD + col) =
                make_float2(b0 * 0.25f, b1 * 0.25f);
        }
    }
}

extern "C" void kernel_launch(void* const* d_in, const int* in_sizes, int n_in,
                              void* d_out, int out_size) {
    const float* inp = (const float*)d_in[0];   // [16,512,4,64]
    const float* W   = (const float*)d_in[1];   // [4,4,64,64]
    float* out = (float*)d_out;

    static int smem_set = 0;
    if (!smem_set) {
        cudaFuncSetAttribute(convattn_fused_kernel,
                             cudaFuncAttributeMaxDynamicSharedMemorySize, SMEM_BYTES);
        smem_set = 1;
    }

    int total4 = INP_ELEMS / 4 + W_ELEMS / 4;
    split_kernel<<<(total4 + THREADS - 1) / THREADS, THREADS>>>(inp, W);

    dim3 grid(LL / LT, BB, NO);   // (16, 16, 4)
    convattn_fused_kernel<<<grid, THREADS, SMEM_BYTES>>>(out);
}